// round 6
// baseline (speedup 1.0000x reference)
#include <cuda_runtime.h>
#include <cuda_fp16.h>
#include <cstdint>

// ============================================================================
// DQSN collapsed: out = A @ w2' + b2*(1-2^-16)
//   A[b,j] = sum_t spike_t(h_in[b,j]) * 2^(t-17),  h_in = x@w1' + b1
// GEMM1: fp16 mma, logical K-tripling [xh|xh|xl]x[wh|wl|wh]  (K'=768)
// GEMM2: fp16 mma, logical K-tripling [Ah|Ah|Al]x[wh|wl|wh]  (K'=3072)
// Near-threshold elements (|v-1|<2e-4 at any IF step) are recomputed with
// sequential fp32 FMA (matches reference rounding; R1 evidence: 4.4e-7) and
// patched into Ah/Al before GEMM2 -> removes the ~8.5e-4 spike-flip floor.
// ============================================================================

#define MDIM 8192
#define IDIM 256
#define HDIM 1024
#define ODIM 256

#define G1_NK 24            // K'=768 in BK=32 tiles
#define G2_NK 96            // K'=3072
#define STRIDE 40           // halves per smem row (80B, ldmatrix conflict-free)
#define FIX_CAP (1 << 18)
#define DELTA 2e-4f

// --------------------------- global scratch (no allocs) ---------------------
__device__ __align__(16) __half g_xh [(size_t)MDIM * IDIM];
__device__ __align__(16) __half g_xl [(size_t)MDIM * IDIM];
__device__ __align__(16) __half g_w1h[(size_t)HDIM * IDIM];
__device__ __align__(16) __half g_w1l[(size_t)HDIM * IDIM];
__device__ __align__(16) __half g_w2h[(size_t)ODIM * HDIM];
__device__ __align__(16) __half g_w2l[(size_t)ODIM * HDIM];
__device__ __align__(16) __half g_Ah [(size_t)MDIM * HDIM];
__device__ __align__(16) __half g_Al [(size_t)MDIM * HDIM];
__device__ int      g_cnt;
__device__ uint32_t g_list[FIX_CAP];

// --------------------------- helpers ----------------------------------------
__device__ __forceinline__ uint32_t smem_addr_u32(const void* p) {
    return (uint32_t)__cvta_generic_to_shared(p);
}
__device__ __forceinline__ void cp16(uint32_t s, const void* g) {
    asm volatile("cp.async.cg.shared.global [%0], [%1], 16;" :: "r"(s), "l"(g));
}
#define CP_COMMIT() asm volatile("cp.async.commit_group;" ::: "memory")
#define CP_WAIT1()  asm volatile("cp.async.wait_group 1;" ::: "memory")

__device__ __forceinline__ void ldm_x4(uint32_t* r, uint32_t addr) {
    asm volatile("ldmatrix.sync.aligned.m8n8.x4.shared.b16 {%0,%1,%2,%3}, [%4];"
        : "=r"(r[0]), "=r"(r[1]), "=r"(r[2]), "=r"(r[3]) : "r"(addr));
}
__device__ __forceinline__ void mma_f16(float* c, const uint32_t* a, const uint32_t* b) {
    asm volatile(
        "mma.sync.aligned.m16n8k16.row.col.f32.f16.f16.f32 "
        "{%0,%1,%2,%3}, {%4,%5,%6,%7}, {%8,%9}, {%0,%1,%2,%3};"
        : "+f"(c[0]), "+f"(c[1]), "+f"(c[2]), "+f"(c[3])
        : "r"(a[0]), "r"(a[1]), "r"(a[2]), "r"(a[3]), "r"(b[0]), "r"(b[1]));
}
__device__ __forceinline__ uint32_t pack_h2(float a, float b) {
    __half2 t = __floats2half2_rn(a, b);
    return *reinterpret_cast<uint32_t*>(&t);
}

// IF neuron closed-form sim
__device__ __forceinline__ float if_sim(float h) {
    float v = 0.0f, av = 0.0f, coef = 0x1p-16f;
#pragma unroll
    for (int t = 0; t < 16; t++) {
        v += h;
        const bool s = (v >= 1.0f);
        av = s ? (av + coef) : av;
        v = s ? 0.0f : v;
        coef += coef;
    }
    return av;
}
// IF sim + near-threshold flag
__device__ __forceinline__ float if_sim_flag(float h, bool& near) {
    float v = 0.0f, av = 0.0f, coef = 0x1p-16f;
#pragma unroll
    for (int t = 0; t < 16; t++) {
        v += h;
        near |= (fabsf(v - 1.0f) < DELTA);
        const bool s = (v >= 1.0f);
        av = s ? (av + coef) : av;
        v = s ? 0.0f : v;
        coef += coef;
    }
    return av;
}

// --------------------------- small kernels -----------------------------------
__global__ void zero_cnt_kernel() { g_cnt = 0; }

// fp32 -> fp16 hi/lo split, row-structure preserved (contiguous)
__global__ __launch_bounds__(256)
void conv_split_kernel(const float* __restrict__ src, __half* __restrict__ dhi,
                       __half* __restrict__ dlo)
{
    const int i = blockIdx.x * blockDim.x + threadIdx.x;  // pair index
    const float2 v = *reinterpret_cast<const float2*>(src + (size_t)i * 2);
    const __half h0 = __float2half_rn(v.x);
    const __half h1 = __float2half_rn(v.y);
    reinterpret_cast<uint32_t*>(dhi)[i] = pack_h2(__half2float(h0), __half2float(h1));
    reinterpret_cast<uint32_t*>(dlo)[i] =
        pack_h2(v.x - __half2float(h0), v.y - __half2float(h1));
}

// Recompute flagged elements with sequential ascending-k fp32 FMA (R1 order).
__global__ __launch_bounds__(256)
void fixup_kernel(const float* __restrict__ x, const float* __restrict__ w1,
                  const float* __restrict__ b1, __half* __restrict__ Ah,
                  __half* __restrict__ Al)
{
    const int i = blockIdx.x * blockDim.x + threadIdx.x;
    int n = g_cnt;
    n = n < FIX_CAP ? n : FIX_CAP;
    if (i >= n) return;
    const uint32_t code = g_list[i];
    const int m = code >> 10, j = code & 1023;
    const float* xr = x + (size_t)m * IDIM;
    const float* wr = w1 + (size_t)j * IDIM;
    float acc = 0.0f;
    for (int k = 0; k < IDIM; k++) acc = fmaf(xr[k], wr[k], acc);
    const float a = if_sim(acc + b1[j]);
    const __half hh = __float2half_rn(a);
    Ah[(size_t)m * HDIM + j] = hh;
    Al[(size_t)m * HDIM + j] = __float2half_rn(a - __half2float(hh));
}

// --------------------------- GEMM1: fp16, 128x128, BK=32 --------------------
// C = [xh|xh|xl] @ [wh|wl|wh]' (K'=768), epilogue: +b1, IF sim (+flag),
// write Ah / Al row-major [8192,1024].
#define G1_STAGE (256 * STRIDE)   // halves

__global__ __launch_bounds__(256, 2)
void gemm1_f16(const __half* __restrict__ Xh, const __half* __restrict__ Xl,
               const __half* __restrict__ Wh, const __half* __restrict__ Wl,
               const float* __restrict__ bias,
               __half* __restrict__ Ah, __half* __restrict__ Al)
{
    __shared__ __half sm[2 * G1_STAGE];   // 40960 B
    const uint32_t smb = smem_addr_u32(sm);

    const int tid = threadIdx.x;
    const int lane = tid & 31;
    const int wid = tid >> 5;
    const int g = lane >> 3, lr = lane & 7;
    const int wm = (wid & 1) * 64, wn = (wid >> 1) * 32;
    const int mblk = blockIdx.y, nblk = blockIdx.x;

    int a_off[4], b_off[2];
#pragma unroll
    for (int ma = 0; ma < 4; ma++)
        a_off[ma] = (wm + ma * 16 + (g & 1) * 8 + lr) * STRIDE + (g >> 1) * 8;
#pragma unroll
    for (int nb = 0; nb < 2; nb++)
        b_off[nb] = (128 + wn + nb * 16 + (g >> 1) * 8 + lr) * STRIDE + (g & 1) * 8;

    float acc[4][4][4];
#pragma unroll
    for (int i = 0; i < 4; i++)
#pragma unroll
        for (int j = 0; j < 4; j++)
#pragma unroll
            for (int k = 0; k < 4; k++) acc[i][j][k] = 0.0f;

    // logical K-tripling: region 0:[xh,wh] 1:[xh,wl] 2:[xl,wh]
    auto load_stage = [&](int s, int kt) {
        const int k0 = kt * 32;
        const int region = k0 >> 8;
        const int koff = k0 & 255;
        const __half* Asrc = (region < 2) ? Xh : Xl;
        const __half* Bsrc = (region == 1) ? Wl : Wh;
#pragma unroll
        for (int i = 0; i < 4; i++) {
            const int c = tid + i * 256;
            const int row = c >> 2, ch = (c & 3) * 8;   // halves
            const __half* gp;
            if (row < 128)
                gp = Asrc + (size_t)(mblk * 128 + row) * IDIM + koff + ch;
            else
                gp = Bsrc + (size_t)(nblk * 128 + (row - 128)) * IDIM + koff + ch;
            cp16(smb + (uint32_t)(s * G1_STAGE + row * STRIDE + ch) * 2, gp);
        }
    };

    load_stage(0, 0);
    CP_COMMIT();
    for (int kt = 0; kt < G1_NK; kt++) {
        if (kt + 1 < G1_NK) load_stage((kt + 1) & 1, kt + 1);
        CP_COMMIT();
        CP_WAIT1();
        __syncthreads();
        const uint32_t stg = smb + (uint32_t)((kt & 1) * G1_STAGE) * 2;
#pragma unroll
        for (int kk = 0; kk < 32; kk += 16) {
            uint32_t a[4][4], b[4][2];
#pragma unroll
            for (int ma = 0; ma < 4; ma++)
                ldm_x4(a[ma], stg + (uint32_t)(a_off[ma] + kk) * 2);
#pragma unroll
            for (int nb = 0; nb < 2; nb++) {
                uint32_t r[4];
                ldm_x4(r, stg + (uint32_t)(b_off[nb] + kk) * 2);
                b[2 * nb][0] = r[0]; b[2 * nb][1] = r[1];
                b[2 * nb + 1][0] = r[2]; b[2 * nb + 1][1] = r[3];
            }
#pragma unroll
            for (int ma = 0; ma < 4; ma++)
#pragma unroll
                for (int na = 0; na < 4; na++) mma_f16(acc[ma][na], a[ma], b[na]);
        }
        __syncthreads();
    }

    // epilogue: +bias, IF sim + flag, exact fp16 hi/lo split of A
    const int gq = lane >> 2, tq = lane & 3;
#pragma unroll
    for (int na = 0; na < 4; na++) {
        const int col = nblk * 128 + wn + na * 8 + 2 * tq;
        const float bb0 = __ldg(bias + col);
        const float bb1 = __ldg(bias + col + 1);
#pragma unroll
        for (int ma = 0; ma < 4; ma++) {
            const int row0 = mblk * 128 + wm + ma * 16 + gq;
#pragma unroll
            for (int rv = 0; rv < 2; rv++) {
                const int row = row0 + rv * 8;
                bool f0 = false, f1 = false;
                const float a0 = if_sim_flag(acc[ma][na][rv * 2 + 0] + bb0, f0);
                const float a1 = if_sim_flag(acc[ma][na][rv * 2 + 1] + bb1, f1);
                const __half h0 = __float2half_rn(a0);   // A has 16 dyadic bits:
                const __half h1 = __float2half_rn(a1);   // fp16 split is EXACT
                const size_t pidx = (size_t)row * (HDIM / 2) + (col >> 1);
                reinterpret_cast<uint32_t*>(Ah)[pidx] = pack_h2(a0, a1);
                reinterpret_cast<uint32_t*>(Al)[pidx] =
                    pack_h2(a0 - __half2float(h0), a1 - __half2float(h1));
                if (f0) {
                    const int idx = atomicAdd(&g_cnt, 1);
                    if (idx < FIX_CAP) g_list[idx] = (uint32_t)(row * 1024 + col);
                }
                if (f1) {
                    const int idx = atomicAdd(&g_cnt, 1);
                    if (idx < FIX_CAP) g_list[idx] = (uint32_t)(row * 1024 + col + 1);
                }
            }
        }
    }
}

// --------------------------- GEMM2: fp16, 128x64, BK=32 ---------------------
// out = [Ah|Ah|Al] @ [wh|wl|wh]' (K'=3072), + b2*(1-2^-16), fp32 [., 256]
#define G2_STAGE (192 * STRIDE)   // halves

__global__ __launch_bounds__(256, 2)
void gemm2_f16(const __half* __restrict__ Ahg, const __half* __restrict__ Alg,
               const __half* __restrict__ Wh, const __half* __restrict__ Wl,
               const float* __restrict__ bias, float* __restrict__ out)
{
    __shared__ __half sm[2 * G2_STAGE];   // 30720 B
    const uint32_t smb = smem_addr_u32(sm);

    const int tid = threadIdx.x;
    const int lane = tid & 31;
    const int wid = tid >> 5;
    const int g = lane >> 3, lr = lane & 7;
    const int wm = (wid & 1) * 64, wn = (wid >> 1) * 16;
    const int mblk = blockIdx.y, nblk = blockIdx.x;

    int a_off[4], b_off;
#pragma unroll
    for (int ma = 0; ma < 4; ma++)
        a_off[ma] = (wm + ma * 16 + (g & 1) * 8 + lr) * STRIDE + (g >> 1) * 8;
    b_off = (128 + wn + (g >> 1) * 8 + lr) * STRIDE + (g & 1) * 8;

    float acc[4][2][4];
#pragma unroll
    for (int i = 0; i < 4; i++)
#pragma unroll
        for (int j = 0; j < 2; j++)
#pragma unroll
            for (int k = 0; k < 4; k++) acc[i][j][k] = 0.0f;

    // logical K-tripling: region 0:[Ah,wh] 1:[Ah,wl] 2:[Al,wh]
    auto load_stage = [&](int s, int kt) {
        const int k0 = kt * 32;
        const int region = k0 >> 10;
        const int koff = k0 & 1023;
        const __half* Asrc = (region < 2) ? Ahg : Alg;
        const __half* Bsrc = (region == 1) ? Wl : Wh;
#pragma unroll
        for (int i = 0; i < 3; i++) {
            const int c = tid + i * 256;
            const int row = c >> 2, ch = (c & 3) * 8;
            const __half* gp;
            if (row < 128)
                gp = Asrc + (size_t)(mblk * 128 + row) * HDIM + koff + ch;
            else
                gp = Bsrc + (size_t)(nblk * 64 + (row - 128)) * HDIM + koff + ch;
            cp16(smb + (uint32_t)(s * G2_STAGE + row * STRIDE + ch) * 2, gp);
        }
    };

    load_stage(0, 0);
    CP_COMMIT();
    for (int kt = 0; kt < G2_NK; kt++) {
        if (kt + 1 < G2_NK) load_stage((kt + 1) & 1, kt + 1);
        CP_COMMIT();
        CP_WAIT1();
        __syncthreads();
        const uint32_t stg = smb + (uint32_t)((kt & 1) * G2_STAGE) * 2;
#pragma unroll
        for (int kk = 0; kk < 32; kk += 16) {
            uint32_t a[4][4], b[2][2];
#pragma unroll
            for (int ma = 0; ma < 4; ma++)
                ldm_x4(a[ma], stg + (uint32_t)(a_off[ma] + kk) * 2);
            {
                uint32_t r[4];
                ldm_x4(r, stg + (uint32_t)(b_off + kk) * 2);
                b[0][0] = r[0]; b[0][1] = r[1];
                b[1][0] = r[2]; b[1][1] = r[3];
            }
#pragma unroll
            for (int ma = 0; ma < 4; ma++)
#pragma unroll
                for (int na = 0; na < 2; na++) mma_f16(acc[ma][na], a[ma], b[na]);
        }
        __syncthreads();
    }

    const float BSCALE = 1.0f - 0x1p-16f;
    const int gq = lane >> 2, tq = lane & 3;
#pragma unroll
    for (int na = 0; na < 2; na++) {
        const int col = nblk * 64 + wn + na * 8 + 2 * tq;
        const float bb0 = __ldg(bias + col) * BSCALE;
        const float bb1 = __ldg(bias + col + 1) * BSCALE;
#pragma unroll
        for (int ma = 0; ma < 4; ma++) {
            const int row0 = mblk * 128 + wm + ma * 16 + gq;
            *reinterpret_cast<float2*>(out + (size_t)row0 * ODIM + col) =
                make_float2(acc[ma][na][0] + bb0, acc[ma][na][1] + bb1);
            *reinterpret_cast<float2*>(out + (size_t)(row0 + 8) * ODIM + col) =
                make_float2(acc[ma][na][2] + bb0, acc[ma][na][3] + bb1);
        }
    }
}

// --------------------------- launch -----------------------------------------
extern "C" void kernel_launch(void* const* d_in, const int* in_sizes, int n_in,
                              void* d_out, int out_size)
{
    const float* x  = (const float*)d_in[0];   // [8192, 256]
    const float* w1 = (const float*)d_in[1];   // [1024, 256]
    const float* b1 = (const float*)d_in[2];   // [1024]
    const float* w2 = (const float*)d_in[3];   // [256, 1024]
    const float* b2 = (const float*)d_in[4];   // [256]
    float* out = (float*)d_out;                // [8192, 256]

    __half *xh, *xl, *w1h, *w1l, *w2h, *w2l, *Ah, *Al;
    cudaGetSymbolAddress((void**)&xh,  g_xh);
    cudaGetSymbolAddress((void**)&xl,  g_xl);
    cudaGetSymbolAddress((void**)&w1h, g_w1h);
    cudaGetSymbolAddress((void**)&w1l, g_w1l);
    cudaGetSymbolAddress((void**)&w2h, g_w2h);
    cudaGetSymbolAddress((void**)&w2l, g_w2l);
    cudaGetSymbolAddress((void**)&Ah,  g_Ah);
    cudaGetSymbolAddress((void**)&Al,  g_Al);

    zero_cnt_kernel<<<1, 1>>>();
    conv_split_kernel<<<MDIM * IDIM / 2 / 256, 256>>>(x,  xh,  xl);
    conv_split_kernel<<<HDIM * IDIM / 2 / 256, 256>>>(w1, w1h, w1l);
    conv_split_kernel<<<ODIM * HDIM / 2 / 256, 256>>>(w2, w2h, w2l);

    gemm1_f16<<<dim3(HDIM / 128, MDIM / 128), 256>>>(xh, xl, w1h, w1l, b1, Ah, Al);
    fixup_kernel<<<FIX_CAP / 256, 256>>>(x, w1, b1, Ah, Al);
    gemm2_f16<<<dim3(ODIM / 64, MDIM / 128), 256>>>(Ah, Al, w2h, w2l, b2, out);
}

// round 8
// speedup vs baseline: 1.4510x; 1.4510x over previous
#include <cuda_runtime.h>
#include <cuda_fp16.h>
#include <cstdint>

// ============================================================================
// DQSN collapsed: out = A @ w2' + b2*(1-2^-16)
//   A[b,j] = sum_t spike_t(h_in[b,j]) * 2^(t-17),  h_in = x@w1' + b1
// GEMM1: fp16 mma, logical K-tripling [xh|xh|xl]x[wh|wl|wh]  (K'=768)
// GEMM2: fp16 mma, logical K-tripling [Ah|Ah|Al]x[wh|wl|wh]  (K'=3072)
// Near-threshold IF elements (|v-1|<1e-4) are recomputed IN-CTA (smem list,
// no global atomics) with sequential fp32 FMA matching reference rounding.
// BK=64, 2-stage cp.async, dynamic smem, fused converter.
// ============================================================================

#define MDIM 8192
#define IDIM 256
#define HDIM 1024
#define ODIM 256

#define G1_NK 12            // K'=768 in BK=64 tiles
#define G2_NK 48            // K'=3072 in BK=64 tiles
#define STRIDE 72           // halves per smem row (144B, ldmatrix conflict-free)
#define G1_STAGE (256 * STRIDE)               // halves
#define G2_STAGE (192 * STRIDE)
#define G1_SMEM (2 * G1_STAGE * 2)            // 73728 B
#define G2_SMEM (2 * G2_STAGE * 2)            // 55296 B
#define FIX_CAP 2048
#define DELTA 1e-4f

// --------------------------- global scratch (no allocs) ---------------------
__device__ __align__(16) __half g_xh [(size_t)MDIM * IDIM];
__device__ __align__(16) __half g_xl [(size_t)MDIM * IDIM];
__device__ __align__(16) __half g_w1h[(size_t)HDIM * IDIM];
__device__ __align__(16) __half g_w1l[(size_t)HDIM * IDIM];
__device__ __align__(16) __half g_w2h[(size_t)ODIM * HDIM];
__device__ __align__(16) __half g_w2l[(size_t)ODIM * HDIM];
__device__ __align__(16) __half g_Ah [(size_t)MDIM * HDIM];
__device__ __align__(16) __half g_Al [(size_t)MDIM * HDIM];

// --------------------------- helpers ----------------------------------------
__device__ __forceinline__ void cp16(uint32_t s, const void* g) {
    asm volatile("cp.async.cg.shared.global [%0], [%1], 16;" :: "r"(s), "l"(g));
}
#define CP_COMMIT() asm volatile("cp.async.commit_group;" ::: "memory")
#define CP_WAIT1()  asm volatile("cp.async.wait_group 1;" ::: "memory")

__device__ __forceinline__ void ldm_x4(uint32_t* r, uint32_t addr) {
    asm volatile("ldmatrix.sync.aligned.m8n8.x4.shared.b16 {%0,%1,%2,%3}, [%4];"
        : "=r"(r[0]), "=r"(r[1]), "=r"(r[2]), "=r"(r[3]) : "r"(addr));
}
__device__ __forceinline__ void mma_f16(float* c, const uint32_t* a, const uint32_t* b) {
    asm volatile(
        "mma.sync.aligned.m16n8k16.row.col.f32.f16.f16.f32 "
        "{%0,%1,%2,%3}, {%4,%5,%6,%7}, {%8,%9}, {%0,%1,%2,%3};"
        : "+f"(c[0]), "+f"(c[1]), "+f"(c[2]), "+f"(c[3])
        : "r"(a[0]), "r"(a[1]), "r"(a[2]), "r"(a[3]), "r"(b[0]), "r"(b[1]));
}
__device__ __forceinline__ uint32_t pack_h2(float a, float b) {
    __half2 t = __floats2half2_rn(a, b);
    return *reinterpret_cast<uint32_t*>(&t);
}

// IF neuron closed-form sim
__device__ __forceinline__ float if_sim(float h) {
    float v = 0.0f, av = 0.0f, coef = 0x1p-16f;
#pragma unroll
    for (int t = 0; t < 16; t++) {
        v += h;
        const bool s = (v >= 1.0f);
        av = s ? (av + coef) : av;
        v = s ? 0.0f : v;
        coef += coef;
    }
    return av;
}
__device__ __forceinline__ float if_sim_flag(float h, bool& near) {
    float v = 0.0f, av = 0.0f, coef = 0x1p-16f;
#pragma unroll
    for (int t = 0; t < 16; t++) {
        v += h;
        near |= (fabsf(v - 1.0f) < DELTA);
        const bool s = (v >= 1.0f);
        av = s ? (av + coef) : av;
        v = s ? 0.0f : v;
        coef += coef;
    }
    return av;
}

// --------------------------- fused converter ---------------------------------
// One kernel splits x, w1, w2 into fp16 hi/lo. Pair-indexed regions.
#define CONV_P1 (MDIM * IDIM / 2)
#define CONV_P2 (HDIM * IDIM / 2)
#define CONV_P3 (ODIM * HDIM / 2)
#define CONV_TOTAL (CONV_P1 + CONV_P2 + CONV_P3)

__global__ __launch_bounds__(256)
void conv_all_kernel(const float* __restrict__ x, const float* __restrict__ w1,
                     const float* __restrict__ w2,
                     __half* __restrict__ xh, __half* __restrict__ xl,
                     __half* __restrict__ w1h, __half* __restrict__ w1l,
                     __half* __restrict__ w2h, __half* __restrict__ w2l)
{
    const int i = blockIdx.x * blockDim.x + threadIdx.x;
    const float* src;
    __half *dhi, *dlo;
    int idx;
    if (i < CONV_P1)               { src = x;  dhi = xh;  dlo = xl;  idx = i; }
    else if (i < CONV_P1 + CONV_P2){ src = w1; dhi = w1h; dlo = w1l; idx = i - CONV_P1; }
    else                           { src = w2; dhi = w2h; dlo = w2l; idx = i - CONV_P1 - CONV_P2; }
    const float2 v = *reinterpret_cast<const float2*>(src + (size_t)idx * 2);
    const __half h0 = __float2half_rn(v.x);
    const __half h1 = __float2half_rn(v.y);
    reinterpret_cast<uint32_t*>(dhi)[idx] = pack_h2(__half2float(h0), __half2float(h1));
    reinterpret_cast<uint32_t*>(dlo)[idx] =
        pack_h2(v.x - __half2float(h0), v.y - __half2float(h1));
}

// --------------------------- GEMM1: fp16, 128x128, BK=64 --------------------
// C = [xh|xh|xl] @ [wh|wl|wh]' (K'=768), epilogue: +b1, IF sim (+flag),
// write Ah/Al row-major; in-CTA fixup of near-threshold elements.
__global__ __launch_bounds__(256, 2)
void gemm1_f16(const __half* __restrict__ Xh, const __half* __restrict__ Xl,
               const __half* __restrict__ Wh, const __half* __restrict__ Wl,
               const float* __restrict__ bias,
               __half* __restrict__ Ah, __half* __restrict__ Al,
               const float* __restrict__ xf, const float* __restrict__ w1f)
{
    extern __shared__ __half sm[];                  // 2 * G1_STAGE halves
    __shared__ int s_cnt;
    __shared__ uint32_t s_list[FIX_CAP];
    const uint32_t smb = (uint32_t)__cvta_generic_to_shared(sm);

    const int tid = threadIdx.x;
    const int lane = tid & 31;
    const int wid = tid >> 5;
    const int g = lane >> 3, lr = lane & 7;
    const int wm = (wid & 1) * 64, wn = (wid >> 1) * 32;
    const int mblk = blockIdx.y, nblk = blockIdx.x;

    if (tid == 0) s_cnt = 0;

    int a_off[4], b_off[2];
#pragma unroll
    for (int ma = 0; ma < 4; ma++)
        a_off[ma] = (wm + ma * 16 + (g & 1) * 8 + lr) * STRIDE + (g >> 1) * 8;
#pragma unroll
    for (int nb = 0; nb < 2; nb++)
        b_off[nb] = (128 + wn + nb * 16 + (g >> 1) * 8 + lr) * STRIDE + (g & 1) * 8;

    float acc[4][4][4];
#pragma unroll
    for (int i = 0; i < 4; i++)
#pragma unroll
        for (int j = 0; j < 4; j++)
#pragma unroll
            for (int k = 0; k < 4; k++) acc[i][j][k] = 0.0f;

    // logical K-tripling: region 0:[xh,wh] 1:[xh,wl] 2:[xl,wh]
    auto load_stage = [&](int s, int kt) {
        const int k0 = kt * 64;
        const int region = k0 >> 8;
        const int koff = k0 & 255;
        const __half* Asrc = (region < 2) ? Xh : Xl;
        const __half* Bsrc = (region == 1) ? Wl : Wh;
#pragma unroll
        for (int i = 0; i < 8; i++) {
            const int c = tid + i * 256;
            const int row = c >> 3, ch = (c & 7) * 8;   // halves
            const __half* gp;
            if (row < 128)
                gp = Asrc + (size_t)(mblk * 128 + row) * IDIM + koff + ch;
            else
                gp = Bsrc + (size_t)(nblk * 128 + (row - 128)) * IDIM + koff + ch;
            cp16(smb + (uint32_t)(s * G1_STAGE + row * STRIDE + ch) * 2, gp);
        }
    };

    load_stage(0, 0);
    CP_COMMIT();
    for (int kt = 0; kt < G1_NK; kt++) {
        if (kt + 1 < G1_NK) load_stage((kt + 1) & 1, kt + 1);
        CP_COMMIT();
        CP_WAIT1();
        __syncthreads();
        const uint32_t stg = smb + (uint32_t)((kt & 1) * G1_STAGE) * 2;
#pragma unroll
        for (int kk = 0; kk < 64; kk += 16) {
            uint32_t a[4][4], b[4][2];
#pragma unroll
            for (int ma = 0; ma < 4; ma++)
                ldm_x4(a[ma], stg + (uint32_t)(a_off[ma] + kk) * 2);
#pragma unroll
            for (int nb = 0; nb < 2; nb++) {
                uint32_t r[4];
                ldm_x4(r, stg + (uint32_t)(b_off[nb] + kk) * 2);
                b[2 * nb][0] = r[0]; b[2 * nb][1] = r[1];
                b[2 * nb + 1][0] = r[2]; b[2 * nb + 1][1] = r[3];
            }
#pragma unroll
            for (int ma = 0; ma < 4; ma++)
#pragma unroll
                for (int na = 0; na < 4; na++) mma_f16(acc[ma][na], a[ma], b[na]);
        }
        __syncthreads();
    }

    // epilogue: +bias, IF sim + flag (smem list), exact fp16 hi/lo split of A
    const int gq = lane >> 2, tq = lane & 3;
#pragma unroll
    for (int na = 0; na < 4; na++) {
        const int col = nblk * 128 + wn + na * 8 + 2 * tq;
        const float bb0 = __ldg(bias + col);
        const float bb1 = __ldg(bias + col + 1);
#pragma unroll
        for (int ma = 0; ma < 4; ma++) {
            const int row0 = mblk * 128 + wm + ma * 16 + gq;
#pragma unroll
            for (int rv = 0; rv < 2; rv++) {
                const int row = row0 + rv * 8;
                bool f0 = false, f1 = false;
                const float a0 = if_sim_flag(acc[ma][na][rv * 2 + 0] + bb0, f0);
                const float a1 = if_sim_flag(acc[ma][na][rv * 2 + 1] + bb1, f1);
                const __half h0 = __float2half_rn(a0);   // A has 16 dyadic bits:
                const __half h1 = __float2half_rn(a1);   // fp16 split is EXACT
                const size_t pidx = (size_t)row * (HDIM / 2) + (col >> 1);
                reinterpret_cast<uint32_t*>(Ah)[pidx] = pack_h2(a0, a1);
                reinterpret_cast<uint32_t*>(Al)[pidx] =
                    pack_h2(a0 - __half2float(h0), a1 - __half2float(h1));
                if (f0) {
                    const int idx = atomicAdd(&s_cnt, 1);
                    if (idx < FIX_CAP) s_list[idx] = (uint32_t)(row * 1024 + col);
                }
                if (f1) {
                    const int idx = atomicAdd(&s_cnt, 1);
                    if (idx < FIX_CAP) s_list[idx] = (uint32_t)(row * 1024 + col + 1);
                }
            }
        }
    }

    // In-CTA fixup: recompute flagged elements with sequential ascending-k
    // fp32 FMA (matches reference rounding; R1 evidence 4.4e-7). This CTA
    // owns all rows/cols it flagged -> no cross-CTA races.
    __syncthreads();
    int n = s_cnt;
    n = n < FIX_CAP ? n : FIX_CAP;
    for (int i = tid; i < n; i += 256) {
        const uint32_t code = s_list[i];
        const int m = code >> 10, j = code & 1023;
        const float* xr = xf + (size_t)m * IDIM;
        const float* wr = w1f + (size_t)j * IDIM;
        float accs = 0.0f;
        for (int k = 0; k < IDIM; k++) accs = fmaf(xr[k], wr[k], accs);
        const float a = if_sim(accs + __ldg(bias + j));
        const __half hh = __float2half_rn(a);
        Ah[(size_t)m * HDIM + j] = hh;
        Al[(size_t)m * HDIM + j] = __float2half_rn(a - __half2float(hh));
    }
}

// --------------------------- GEMM2: fp16, 128x64, BK=64 ---------------------
// out = [Ah|Ah|Al] @ [wh|wl|wh]' (K'=3072), + b2*(1-2^-16), fp32 [., 256]
__global__ __launch_bounds__(256, 2)
void gemm2_f16(const __half* __restrict__ Ahg, const __half* __restrict__ Alg,
               const __half* __restrict__ Wh, const __half* __restrict__ Wl,
               const float* __restrict__ bias, float* __restrict__ out)
{
    extern __shared__ __half sm[];                  // 2 * G2_STAGE halves
    const uint32_t smb = (uint32_t)__cvta_generic_to_shared(sm);

    const int tid = threadIdx.x;
    const int lane = tid & 31;
    const int wid = tid >> 5;
    const int g = lane >> 3, lr = lane & 7;
    const int wm = (wid & 1) * 64, wn = (wid >> 1) * 16;
    const int mblk = blockIdx.y, nblk = blockIdx.x;

    int a_off[4], b_off;
#pragma unroll
    for (int ma = 0; ma < 4; ma++)
        a_off[ma] = (wm + ma * 16 + (g & 1) * 8 + lr) * STRIDE + (g >> 1) * 8;
    b_off = (128 + wn + (g >> 1) * 8 + lr) * STRIDE + (g & 1) * 8;

    float acc[4][2][4];
#pragma unroll
    for (int i = 0; i < 4; i++)
#pragma unroll
        for (int j = 0; j < 2; j++)
#pragma unroll
            for (int k = 0; k < 4; k++) acc[i][j][k] = 0.0f;

    // logical K-tripling: region 0:[Ah,wh] 1:[Ah,wl] 2:[Al,wh]
    auto load_stage = [&](int s, int kt) {
        const int k0 = kt * 64;
        const int region = k0 >> 10;
        const int koff = k0 & 1023;
        const __half* Asrc = (region < 2) ? Ahg : Alg;
        const __half* Bsrc = (region == 1) ? Wl : Wh;
#pragma unroll
        for (int i = 0; i < 6; i++) {
            const int c = tid + i * 256;
            const int row = c >> 3, ch = (c & 7) * 8;
            const __half* gp;
            if (row < 128)
                gp = Asrc + (size_t)(mblk * 128 + row) * HDIM + koff + ch;
            else
                gp = Bsrc + (size_t)(nblk * 64 + (row - 128)) * HDIM + koff + ch;
            cp16(smb + (uint32_t)(s * G2_STAGE + row * STRIDE + ch) * 2, gp);
        }
    };

    load_stage(0, 0);
    CP_COMMIT();
    for (int kt = 0; kt < G2_NK; kt++) {
        if (kt + 1 < G2_NK) load_stage((kt + 1) & 1, kt + 1);
        CP_COMMIT();
        CP_WAIT1();
        __syncthreads();
        const uint32_t stg = smb + (uint32_t)((kt & 1) * G2_STAGE) * 2;
#pragma unroll
        for (int kk = 0; kk < 64; kk += 16) {
            uint32_t a[4][4], b[2][2];
#pragma unroll
            for (int ma = 0; ma < 4; ma++)
                ldm_x4(a[ma], stg + (uint32_t)(a_off[ma] + kk) * 2);
            {
                uint32_t r[4];
                ldm_x4(r, stg + (uint32_t)(b_off + kk) * 2);
                b[0][0] = r[0]; b[0][1] = r[1];
                b[1][0] = r[2]; b[1][1] = r[3];
            }
#pragma unroll
            for (int ma = 0; ma < 4; ma++)
#pragma unroll
                for (int na = 0; na < 2; na++) mma_f16(acc[ma][na], a[ma], b[na]);
        }
        __syncthreads();
    }

    const float BSCALE = 1.0f - 0x1p-16f;
    const int gq = lane >> 2, tq = lane & 3;
#pragma unroll
    for (int na = 0; na < 2; na++) {
        const int col = nblk * 64 + wn + na * 8 + 2 * tq;
        const float bb0 = __ldg(bias + col) * BSCALE;
        const float bb1 = __ldg(bias + col + 1) * BSCALE;
#pragma unroll
        for (int ma = 0; ma < 4; ma++) {
            const int row0 = mblk * 128 + wm + ma * 16 + gq;
            *reinterpret_cast<float2*>(out + (size_t)row0 * ODIM + col) =
                make_float2(acc[ma][na][0] + bb0, acc[ma][na][1] + bb1);
            *reinterpret_cast<float2*>(out + (size_t)(row0 + 8) * ODIM + col) =
                make_float2(acc[ma][na][2] + bb0, acc[ma][na][3] + bb1);
        }
    }
}

// --------------------------- launch -----------------------------------------
extern "C" void kernel_launch(void* const* d_in, const int* in_sizes, int n_in,
                              void* d_out, int out_size)
{
    const float* x  = (const float*)d_in[0];   // [8192, 256]
    const float* w1 = (const float*)d_in[1];   // [1024, 256]
    const float* b1 = (const float*)d_in[2];   // [1024]
    const float* w2 = (const float*)d_in[3];   // [256, 1024]
    const float* b2 = (const float*)d_in[4];   // [256]
    float* out = (float*)d_out;                // [8192, 256]

    __half *xh, *xl, *w1h, *w1l, *w2h, *w2l, *Ah, *Al;
    cudaGetSymbolAddress((void**)&xh,  g_xh);
    cudaGetSymbolAddress((void**)&xl,  g_xl);
    cudaGetSymbolAddress((void**)&w1h, g_w1h);
    cudaGetSymbolAddress((void**)&w1l, g_w1l);
    cudaGetSymbolAddress((void**)&w2h, g_w2h);
    cudaGetSymbolAddress((void**)&w2l, g_w2l);
    cudaGetSymbolAddress((void**)&Ah,  g_Ah);
    cudaGetSymbolAddress((void**)&Al,  g_Al);

    cudaFuncSetAttribute(gemm1_f16,
                         cudaFuncAttributeMaxDynamicSharedMemorySize, G1_SMEM);
    cudaFuncSetAttribute(gemm2_f16,
                         cudaFuncAttributeMaxDynamicSharedMemorySize, G2_SMEM);

    conv_all_kernel<<<CONV_TOTAL / 256, 256>>>(x, w1, w2, xh, xl, w1h, w1l, w2h, w2l);

    gemm1_f16<<<dim3(HDIM / 128, MDIM / 128), 256, G1_SMEM>>>(
        xh, xl, w1h, w1l, b1, Ah, Al, x, w1);

    gemm2_f16<<<dim3(ODIM / 64, MDIM / 128), 256, G2_SMEM>>>(
        Ah, Al, w2h, w2l, b2, out);
}

// round 9
// speedup vs baseline: 1.9007x; 1.3099x over previous
#include <cuda_runtime.h>
#include <cuda_fp16.h>
#include <cstdint>

// ============================================================================
// DQSN collapsed: out = A @ w2' + b2*(1-2^-16)
//   A[b,j] = sum_t spike_t(h_in[b,j]) * 2^(t-17),  h_in = x@w1' + b1
// GEMM1: fp16 mma, logical K-tripling [xh|xh|xl]x[wh|wl|wh] (K'=768, err ~1e-7)
// GEMM2: fp16 mma, 2-product Ah·wh + Ah·wl (K'=2048): dropping Al·w costs
//   ~1.5e-4 rel (norm), 6x under gate. A-slab loaded ONCE per k-tile and used
//   against both Wh and Wl (shared-A stage: 128 A rows + 64 Wh + 64 Wl).
// Near-threshold IF elements (|v-1|<1e-4) recomputed in-CTA with sequential
// fp32 FMA (matches reference rounding; R6/R8 evidence).
// Both GEMMs sit at the mma.sync tensor ceiling (~30% pipe) -> wins come from
// MAC-count reduction, which this round does (-33% in GEMM2).
// ============================================================================

#define MDIM 8192
#define IDIM 256
#define HDIM 1024
#define ODIM 256

#define G1_NK 12            // K'=768 in BK=64 tiles
#define G2_NK 16            // K=1024 physical tiles (2 products per tile)
#define STRIDE 72           // halves per smem row (144B, ldmatrix conflict-free)
#define G1_STAGE (256 * STRIDE)               // halves: 128 A + 128 B rows
#define G2_STAGE (256 * STRIDE)               // halves: 128 A + 64 Wh + 64 Wl
#define G1_SMEM (2 * G1_STAGE * 2)            // 73728 B
#define G2_SMEM (2 * G2_STAGE * 2)            // 73728 B
#define FIX_CAP 2048
#define DELTA 1e-4f

// --------------------------- global scratch (no allocs) ---------------------
__device__ __align__(16) __half g_xh [(size_t)MDIM * IDIM];
__device__ __align__(16) __half g_xl [(size_t)MDIM * IDIM];
__device__ __align__(16) __half g_w1h[(size_t)HDIM * IDIM];
__device__ __align__(16) __half g_w1l[(size_t)HDIM * IDIM];
__device__ __align__(16) __half g_w2h[(size_t)ODIM * HDIM];
__device__ __align__(16) __half g_w2l[(size_t)ODIM * HDIM];
__device__ __align__(16) __half g_Ah [(size_t)MDIM * HDIM];

// --------------------------- helpers ----------------------------------------
__device__ __forceinline__ void cp16(uint32_t s, const void* g) {
    asm volatile("cp.async.cg.shared.global [%0], [%1], 16;" :: "r"(s), "l"(g));
}
#define CP_COMMIT() asm volatile("cp.async.commit_group;" ::: "memory")
#define CP_WAIT1()  asm volatile("cp.async.wait_group 1;" ::: "memory")

__device__ __forceinline__ void ldm_x4(uint32_t* r, uint32_t addr) {
    asm volatile("ldmatrix.sync.aligned.m8n8.x4.shared.b16 {%0,%1,%2,%3}, [%4];"
        : "=r"(r[0]), "=r"(r[1]), "=r"(r[2]), "=r"(r[3]) : "r"(addr));
}
__device__ __forceinline__ void mma_f16(float* c, const uint32_t* a, const uint32_t* b) {
    asm volatile(
        "mma.sync.aligned.m16n8k16.row.col.f32.f16.f16.f32 "
        "{%0,%1,%2,%3}, {%4,%5,%6,%7}, {%8,%9}, {%0,%1,%2,%3};"
        : "+f"(c[0]), "+f"(c[1]), "+f"(c[2]), "+f"(c[3])
        : "r"(a[0]), "r"(a[1]), "r"(a[2]), "r"(a[3]), "r"(b[0]), "r"(b[1]));
}
__device__ __forceinline__ uint32_t pack_h2(float a, float b) {
    __half2 t = __floats2half2_rn(a, b);
    return *reinterpret_cast<uint32_t*>(&t);
}

// IF neuron closed-form sim
__device__ __forceinline__ float if_sim(float h) {
    float v = 0.0f, av = 0.0f, coef = 0x1p-16f;
#pragma unroll
    for (int t = 0; t < 16; t++) {
        v += h;
        const bool s = (v >= 1.0f);
        av = s ? (av + coef) : av;
        v = s ? 0.0f : v;
        coef += coef;
    }
    return av;
}
__device__ __forceinline__ float if_sim_flag(float h, bool& near) {
    float v = 0.0f, av = 0.0f, coef = 0x1p-16f;
#pragma unroll
    for (int t = 0; t < 16; t++) {
        v += h;
        near |= (fabsf(v - 1.0f) < DELTA);
        const bool s = (v >= 1.0f);
        av = s ? (av + coef) : av;
        v = s ? 0.0f : v;
        coef += coef;
    }
    return av;
}

// --------------------------- fused converter ---------------------------------
#define CONV_P1 (MDIM * IDIM / 2)
#define CONV_P2 (HDIM * IDIM / 2)
#define CONV_P3 (ODIM * HDIM / 2)
#define CONV_TOTAL (CONV_P1 + CONV_P2 + CONV_P3)

__global__ __launch_bounds__(256)
void conv_all_kernel(const float* __restrict__ x, const float* __restrict__ w1,
                     const float* __restrict__ w2,
                     __half* __restrict__ xh, __half* __restrict__ xl,
                     __half* __restrict__ w1h, __half* __restrict__ w1l,
                     __half* __restrict__ w2h, __half* __restrict__ w2l)
{
    const int i = blockIdx.x * blockDim.x + threadIdx.x;
    const float* src;
    __half *dhi, *dlo;
    int idx;
    if (i < CONV_P1)               { src = x;  dhi = xh;  dlo = xl;  idx = i; }
    else if (i < CONV_P1 + CONV_P2){ src = w1; dhi = w1h; dlo = w1l; idx = i - CONV_P1; }
    else                           { src = w2; dhi = w2h; dlo = w2l; idx = i - CONV_P1 - CONV_P2; }
    const float2 v = *reinterpret_cast<const float2*>(src + (size_t)idx * 2);
    const __half h0 = __float2half_rn(v.x);
    const __half h1 = __float2half_rn(v.y);
    reinterpret_cast<uint32_t*>(dhi)[idx] = pack_h2(__half2float(h0), __half2float(h1));
    reinterpret_cast<uint32_t*>(dlo)[idx] =
        pack_h2(v.x - __half2float(h0), v.y - __half2float(h1));
}

// --------------------------- GEMM1: fp16, 128x128, BK=64 --------------------
// C = [xh|xh|xl] @ [wh|wl|wh]' (K'=768), epilogue: +b1, IF sim (+flag),
// write Ah row-major; in-CTA fixup of near-threshold elements.
__global__ __launch_bounds__(256, 2)
void gemm1_f16(const __half* __restrict__ Xh, const __half* __restrict__ Xl,
               const __half* __restrict__ Wh, const __half* __restrict__ Wl,
               const float* __restrict__ bias, __half* __restrict__ Ah,
               const float* __restrict__ xf, const float* __restrict__ w1f)
{
    extern __shared__ __half sm[];                  // 2 * G1_STAGE halves
    __shared__ int s_cnt;
    __shared__ uint32_t s_list[FIX_CAP];
    const uint32_t smb = (uint32_t)__cvta_generic_to_shared(sm);

    const int tid = threadIdx.x;
    const int lane = tid & 31;
    const int wid = tid >> 5;
    const int g = lane >> 3, lr = lane & 7;
    const int wm = (wid & 1) * 64, wn = (wid >> 1) * 32;
    const int mblk = blockIdx.y, nblk = blockIdx.x;

    if (tid == 0) s_cnt = 0;

    int a_off[4], b_off[2];
#pragma unroll
    for (int ma = 0; ma < 4; ma++)
        a_off[ma] = (wm + ma * 16 + (g & 1) * 8 + lr) * STRIDE + (g >> 1) * 8;
#pragma unroll
    for (int nb = 0; nb < 2; nb++)
        b_off[nb] = (128 + wn + nb * 16 + (g >> 1) * 8 + lr) * STRIDE + (g & 1) * 8;

    float acc[4][4][4];
#pragma unroll
    for (int i = 0; i < 4; i++)
#pragma unroll
        for (int j = 0; j < 4; j++)
#pragma unroll
            for (int k = 0; k < 4; k++) acc[i][j][k] = 0.0f;

    // logical K-tripling: region 0:[xh,wh] 1:[xh,wl] 2:[xl,wh]
    auto load_stage = [&](int s, int kt) {
        const int k0 = kt * 64;
        const int region = k0 >> 8;
        const int koff = k0 & 255;
        const __half* Asrc = (region < 2) ? Xh : Xl;
        const __half* Bsrc = (region == 1) ? Wl : Wh;
#pragma unroll
        for (int i = 0; i < 8; i++) {
            const int c = tid + i * 256;
            const int row = c >> 3, ch = (c & 7) * 8;   // halves
            const __half* gp;
            if (row < 128)
                gp = Asrc + (size_t)(mblk * 128 + row) * IDIM + koff + ch;
            else
                gp = Bsrc + (size_t)(nblk * 128 + (row - 128)) * IDIM + koff + ch;
            cp16(smb + (uint32_t)(s * G1_STAGE + row * STRIDE + ch) * 2, gp);
        }
    };

    load_stage(0, 0);
    CP_COMMIT();
    for (int kt = 0; kt < G1_NK; kt++) {
        if (kt + 1 < G1_NK) load_stage((kt + 1) & 1, kt + 1);
        CP_COMMIT();
        CP_WAIT1();
        __syncthreads();
        const uint32_t stg = smb + (uint32_t)((kt & 1) * G1_STAGE) * 2;
#pragma unroll
        for (int kk = 0; kk < 64; kk += 16) {
            uint32_t a[4][4], b[4][2];
#pragma unroll
            for (int ma = 0; ma < 4; ma++)
                ldm_x4(a[ma], stg + (uint32_t)(a_off[ma] + kk) * 2);
#pragma unroll
            for (int nb = 0; nb < 2; nb++) {
                uint32_t r[4];
                ldm_x4(r, stg + (uint32_t)(b_off[nb] + kk) * 2);
                b[2 * nb][0] = r[0]; b[2 * nb][1] = r[1];
                b[2 * nb + 1][0] = r[2]; b[2 * nb + 1][1] = r[3];
            }
#pragma unroll
            for (int ma = 0; ma < 4; ma++)
#pragma unroll
                for (int na = 0; na < 4; na++) mma_f16(acc[ma][na], a[ma], b[na]);
        }
        __syncthreads();
    }

    // epilogue: +bias, IF sim + flag (smem list), write Ah (fp16 round; the
    // dropped Al residual is covered by GEMM2's error budget)
    const int gq = lane >> 2, tq = lane & 3;
#pragma unroll
    for (int na = 0; na < 4; na++) {
        const int col = nblk * 128 + wn + na * 8 + 2 * tq;
        const float bb0 = __ldg(bias + col);
        const float bb1 = __ldg(bias + col + 1);
#pragma unroll
        for (int ma = 0; ma < 4; ma++) {
            const int row0 = mblk * 128 + wm + ma * 16 + gq;
#pragma unroll
            for (int rv = 0; rv < 2; rv++) {
                const int row = row0 + rv * 8;
                bool f0 = false, f1 = false;
                const float a0 = if_sim_flag(acc[ma][na][rv * 2 + 0] + bb0, f0);
                const float a1 = if_sim_flag(acc[ma][na][rv * 2 + 1] + bb1, f1);
                const size_t pidx = (size_t)row * (HDIM / 2) + (col >> 1);
                reinterpret_cast<uint32_t*>(Ah)[pidx] = pack_h2(a0, a1);
                if (f0) {
                    const int idx = atomicAdd(&s_cnt, 1);
                    if (idx < FIX_CAP) s_list[idx] = (uint32_t)(row * 1024 + col);
                }
                if (f1) {
                    const int idx = atomicAdd(&s_cnt, 1);
                    if (idx < FIX_CAP) s_list[idx] = (uint32_t)(row * 1024 + col + 1);
                }
            }
        }
    }

    // In-CTA fixup: recompute flagged elements with sequential ascending-k
    // fp32 FMA (matches reference rounding). CTA owns its tile -> no races.
    __syncthreads();
    int n = s_cnt;
    n = n < FIX_CAP ? n : FIX_CAP;
    for (int i = tid; i < n; i += 256) {
        const uint32_t code = s_list[i];
        const int m = code >> 10, j = code & 1023;
        const float* xr = xf + (size_t)m * IDIM;
        const float* wr = w1f + (size_t)j * IDIM;
        float accs = 0.0f;
        for (int k = 0; k < IDIM; k++) accs = fmaf(xr[k], wr[k], accs);
        const float a = if_sim(accs + __ldg(bias + j));
        Ah[(size_t)m * HDIM + j] = __float2half_rn(a);
    }
}

// --------------------------- GEMM2: fp16, 128x64, shared-A ------------------
// out = Ah @ (wh+wl)' over K=1024: per k-tile load Ah slab ONCE + Wh + Wl
// slabs; both products accumulate into the same fp32 acc.
// Stage rows: [0,128) Ah, [128,192) Wh, [192,256) Wl.
__global__ __launch_bounds__(256, 2)
void gemm2_f16(const __half* __restrict__ Ahg,
               const __half* __restrict__ Wh, const __half* __restrict__ Wl,
               const float* __restrict__ bias, float* __restrict__ out)
{
    extern __shared__ __half sm[];                  // 2 * G2_STAGE halves
    const uint32_t smb = (uint32_t)__cvta_generic_to_shared(sm);

    const int tid = threadIdx.x;
    const int lane = tid & 31;
    const int wid = tid >> 5;
    const int g = lane >> 3, lr = lane & 7;
    const int wm = (wid & 1) * 64, wn = (wid >> 1) * 16;
    const int mblk = blockIdx.y, nblk = blockIdx.x;

    int a_off[4];
#pragma unroll
    for (int ma = 0; ma < 4; ma++)
        a_off[ma] = (wm + ma * 16 + (g & 1) * 8 + lr) * STRIDE + (g >> 1) * 8;
    const int b_off_h = (128 + wn + (g >> 1) * 8 + lr) * STRIDE + (g & 1) * 8;
    const int b_off_l = b_off_h + 64 * STRIDE;

    float acc[4][2][4];
#pragma unroll
    for (int i = 0; i < 4; i++)
#pragma unroll
        for (int j = 0; j < 2; j++)
#pragma unroll
            for (int k = 0; k < 4; k++) acc[i][j][k] = 0.0f;

    // stage: 2048 16B-chunks, 8 per thread
    auto load_stage = [&](int s, int kt) {
        const int k0 = kt * 64;
#pragma unroll
        for (int i = 0; i < 8; i++) {
            const int c = tid + i * 256;
            const int row = c >> 3, ch = (c & 7) * 8;
            const __half* gp;
            if (row < 128)
                gp = Ahg + (size_t)(mblk * 128 + row) * HDIM + k0 + ch;
            else if (row < 192)
                gp = Wh + (size_t)(nblk * 64 + (row - 128)) * HDIM + k0 + ch;
            else
                gp = Wl + (size_t)(nblk * 64 + (row - 192)) * HDIM + k0 + ch;
            cp16(smb + (uint32_t)(s * G2_STAGE + row * STRIDE + ch) * 2, gp);
        }
    };

    load_stage(0, 0);
    CP_COMMIT();
    for (int kt = 0; kt < G2_NK; kt++) {
        if (kt + 1 < G2_NK) load_stage((kt + 1) & 1, kt + 1);
        CP_COMMIT();
        CP_WAIT1();
        __syncthreads();
        const uint32_t stg = smb + (uint32_t)((kt & 1) * G2_STAGE) * 2;
#pragma unroll
        for (int kk = 0; kk < 64; kk += 16) {
            uint32_t a[4][4], bh[2][2], bl[2][2];
#pragma unroll
            for (int ma = 0; ma < 4; ma++)
                ldm_x4(a[ma], stg + (uint32_t)(a_off[ma] + kk) * 2);
            {
                uint32_t r[4];
                ldm_x4(r, stg + (uint32_t)(b_off_h + kk) * 2);
                bh[0][0] = r[0]; bh[0][1] = r[1];
                bh[1][0] = r[2]; bh[1][1] = r[3];
                ldm_x4(r, stg + (uint32_t)(b_off_l + kk) * 2);
                bl[0][0] = r[0]; bl[0][1] = r[1];
                bl[1][0] = r[2]; bl[1][1] = r[3];
            }
#pragma unroll
            for (int ma = 0; ma < 4; ma++)
#pragma unroll
                for (int na = 0; na < 2; na++) {
                    mma_f16(acc[ma][na], a[ma], bh[na]);
                    mma_f16(acc[ma][na], a[ma], bl[na]);
                }
        }
        __syncthreads();
    }

    const float BSCALE = 1.0f - 0x1p-16f;
    const int gq = lane >> 2, tq = lane & 3;
#pragma unroll
    for (int na = 0; na < 2; na++) {
        const int col = nblk * 64 + wn + na * 8 + 2 * tq;
        const float bb0 = __ldg(bias + col) * BSCALE;
        const float bb1 = __ldg(bias + col + 1) * BSCALE;
#pragma unroll
        for (int ma = 0; ma < 4; ma++) {
            const int row0 = mblk * 128 + wm + ma * 16 + gq;
            *reinterpret_cast<float2*>(out + (size_t)row0 * ODIM + col) =
                make_float2(acc[ma][na][0] + bb0, acc[ma][na][1] + bb1);
            *reinterpret_cast<float2*>(out + (size_t)(row0 + 8) * ODIM + col) =
                make_float2(acc[ma][na][2] + bb0, acc[ma][na][3] + bb1);
        }
    }
}

// --------------------------- launch -----------------------------------------
extern "C" void kernel_launch(void* const* d_in, const int* in_sizes, int n_in,
                              void* d_out, int out_size)
{
    const float* x  = (const float*)d_in[0];   // [8192, 256]
    const float* w1 = (const float*)d_in[1];   // [1024, 256]
    const float* b1 = (const float*)d_in[2];   // [1024]
    const float* w2 = (const float*)d_in[3];   // [256, 1024]
    const float* b2 = (const float*)d_in[4];   // [256]
    float* out = (float*)d_out;                // [8192, 256]

    __half *xh, *xl, *w1h, *w1l, *w2h, *w2l, *Ah;
    cudaGetSymbolAddress((void**)&xh,  g_xh);
    cudaGetSymbolAddress((void**)&xl,  g_xl);
    cudaGetSymbolAddress((void**)&w1h, g_w1h);
    cudaGetSymbolAddress((void**)&w1l, g_w1l);
    cudaGetSymbolAddress((void**)&w2h, g_w2h);
    cudaGetSymbolAddress((void**)&w2l, g_w2l);
    cudaGetSymbolAddress((void**)&Ah,  g_Ah);

    cudaFuncSetAttribute(gemm1_f16,
                         cudaFuncAttributeMaxDynamicSharedMemorySize, G1_SMEM);
    cudaFuncSetAttribute(gemm2_f16,
                         cudaFuncAttributeMaxDynamicSharedMemorySize, G2_SMEM);

    conv_all_kernel<<<CONV_TOTAL / 256, 256>>>(x, w1, w2, xh, xl, w1h, w1l, w2h, w2l);

    gemm1_f16<<<dim3(HDIM / 128, MDIM / 128), 256, G1_SMEM>>>(
        xh, xl, w1h, w1l, b1, Ah, x, w1);

    gemm2_f16<<<dim3(ODIM / 64, MDIM / 128), 256, G2_SMEM>>>(
        Ah, w2h, w2l, b2, out);
}

// round 10
// speedup vs baseline: 2.0974x; 1.1035x over previous
#include <cuda_runtime.h>
#include <cuda_fp16.h>
#include <cstdint>

// ============================================================================
// DQSN collapsed: out = A @ w2' + b2*(1-2^-16)
//   A[b,j] = sum_t spike_t(h_in[b,j]) * 2^(t-17),  h_in = x@w1' + b1
// GEMM1: fp16 mma, logical K-tripling [xh|xh|xl]x[wh|wl|wh] (K'=768) --
//   3 products are load-bearing: they keep v-error << DELTA at the IF boundary.
// GEMM2: single-product fp16 Ah @ wh' (K=1024). Dropped Al+wl terms cost
//   ~3.1e-4 rel total (calibrated: R9 measured 1.32e-4 for Al alone).
// Near-threshold IF elements (|v-1|<1e-4) recomputed in-CTA with sequential
// fp32 FMA (matches reference rounding; R6/R8/R9 evidence).
// Pipeline: ONE __syncthreads per k-tile (wait0; sync; issue-next; compute) --
// next-tile cp.async overlaps the whole current-tile compute.
// ============================================================================

#define MDIM 8192
#define IDIM 256
#define HDIM 1024
#define ODIM 256

#define G1_NK 12            // K'=768 in BK=64 tiles
#define G2_NK 16            // K=1024 in BK=64 tiles
#define STRIDE 72           // halves per smem row (144B, ldmatrix conflict-free)
#define G1_STAGE (256 * STRIDE)               // halves: 128 A + 128 B rows
#define G2_STAGE (192 * STRIDE)               // halves: 128 A + 64 W rows
#define G1_SMEM (2 * G1_STAGE * 2)            // 73728 B
#define G2_SMEM (2 * G2_STAGE * 2)            // 55296 B
#define FIX_CAP 2048
#define DELTA 1e-4f

// --------------------------- global scratch (no allocs) ---------------------
__device__ __align__(16) __half g_xh [(size_t)MDIM * IDIM];
__device__ __align__(16) __half g_xl [(size_t)MDIM * IDIM];
__device__ __align__(16) __half g_w1h[(size_t)HDIM * IDIM];
__device__ __align__(16) __half g_w1l[(size_t)HDIM * IDIM];
__device__ __align__(16) __half g_w2h[(size_t)ODIM * HDIM];
__device__ __align__(16) __half g_Ah [(size_t)MDIM * HDIM];

// --------------------------- helpers ----------------------------------------
__device__ __forceinline__ void cp16(uint32_t s, const void* g) {
    asm volatile("cp.async.cg.shared.global [%0], [%1], 16;" :: "r"(s), "l"(g));
}
#define CP_COMMIT() asm volatile("cp.async.commit_group;" ::: "memory")
#define CP_WAIT0()  asm volatile("cp.async.wait_group 0;" ::: "memory")

__device__ __forceinline__ void ldm_x4(uint32_t* r, uint32_t addr) {
    asm volatile("ldmatrix.sync.aligned.m8n8.x4.shared.b16 {%0,%1,%2,%3}, [%4];"
        : "=r"(r[0]), "=r"(r[1]), "=r"(r[2]), "=r"(r[3]) : "r"(addr));
}
__device__ __forceinline__ void mma_f16(float* c, const uint32_t* a, const uint32_t* b) {
    asm volatile(
        "mma.sync.aligned.m16n8k16.row.col.f32.f16.f16.f32 "
        "{%0,%1,%2,%3}, {%4,%5,%6,%7}, {%8,%9}, {%0,%1,%2,%3};"
        : "+f"(c[0]), "+f"(c[1]), "+f"(c[2]), "+f"(c[3])
        : "r"(a[0]), "r"(a[1]), "r"(a[2]), "r"(a[3]), "r"(b[0]), "r"(b[1]));
}
__device__ __forceinline__ uint32_t pack_h2(float a, float b) {
    __half2 t = __floats2half2_rn(a, b);
    return *reinterpret_cast<uint32_t*>(&t);
}

// IF neuron closed-form sim
__device__ __forceinline__ float if_sim(float h) {
    float v = 0.0f, av = 0.0f, coef = 0x1p-16f;
#pragma unroll
    for (int t = 0; t < 16; t++) {
        v += h;
        const bool s = (v >= 1.0f);
        av = s ? (av + coef) : av;
        v = s ? 0.0f : v;
        coef += coef;
    }
    return av;
}
__device__ __forceinline__ float if_sim_flag(float h, bool& near) {
    float v = 0.0f, av = 0.0f, coef = 0x1p-16f;
#pragma unroll
    for (int t = 0; t < 16; t++) {
        v += h;
        near |= (fabsf(v - 1.0f) < DELTA);
        const bool s = (v >= 1.0f);
        av = s ? (av + coef) : av;
        v = s ? 0.0f : v;
        coef += coef;
    }
    return av;
}

// --------------------------- fused converter ---------------------------------
#define CONV_P1 (MDIM * IDIM / 2)
#define CONV_P2 (HDIM * IDIM / 2)
#define CONV_P3 (ODIM * HDIM / 2)
#define CONV_TOTAL (CONV_P1 + CONV_P2 + CONV_P3)

__global__ __launch_bounds__(256)
void conv_all_kernel(const float* __restrict__ x, const float* __restrict__ w1,
                     const float* __restrict__ w2,
                     __half* __restrict__ xh, __half* __restrict__ xl,
                     __half* __restrict__ w1h, __half* __restrict__ w1l,
                     __half* __restrict__ w2h)
{
    const int i = blockIdx.x * blockDim.x + threadIdx.x;
    if (i < CONV_P1 + CONV_P2) {
        const float* src;
        __half *dhi, *dlo;
        int idx;
        if (i < CONV_P1) { src = x;  dhi = xh;  dlo = xl;  idx = i; }
        else             { src = w1; dhi = w1h; dlo = w1l; idx = i - CONV_P1; }
        const float2 v = *reinterpret_cast<const float2*>(src + (size_t)idx * 2);
        const __half h0 = __float2half_rn(v.x);
        const __half h1 = __float2half_rn(v.y);
        reinterpret_cast<uint32_t*>(dhi)[idx] =
            pack_h2(__half2float(h0), __half2float(h1));
        reinterpret_cast<uint32_t*>(dlo)[idx] =
            pack_h2(v.x - __half2float(h0), v.y - __half2float(h1));
    } else {
        const int idx = i - CONV_P1 - CONV_P2;     // w2: hi only
        const float2 v = *reinterpret_cast<const float2*>(w2 + (size_t)idx * 2);
        reinterpret_cast<uint32_t*>(w2h)[idx] = pack_h2(v.x, v.y);
    }
}

// --------------------------- GEMM1: fp16, 128x128, BK=64 --------------------
// C = [xh|xh|xl] @ [wh|wl|wh]' (K'=768), epilogue: +b1, IF sim (+flag),
// write Ah row-major; in-CTA fixup of near-threshold elements.
__global__ __launch_bounds__(256, 2)
void gemm1_f16(const __half* __restrict__ Xh, const __half* __restrict__ Xl,
               const __half* __restrict__ Wh, const __half* __restrict__ Wl,
               const float* __restrict__ bias, __half* __restrict__ Ah,
               const float* __restrict__ xf, const float* __restrict__ w1f)
{
    extern __shared__ __half sm[];                  // 2 * G1_STAGE halves
    __shared__ int s_cnt;
    __shared__ uint32_t s_list[FIX_CAP];
    const uint32_t smb = (uint32_t)__cvta_generic_to_shared(sm);

    const int tid = threadIdx.x;
    const int lane = tid & 31;
    const int wid = tid >> 5;
    const int g = lane >> 3, lr = lane & 7;
    const int wm = (wid & 1) * 64, wn = (wid >> 1) * 32;
    const int mblk = blockIdx.y, nblk = blockIdx.x;

    if (tid == 0) s_cnt = 0;

    int a_off[4], b_off[2];
#pragma unroll
    for (int ma = 0; ma < 4; ma++)
        a_off[ma] = (wm + ma * 16 + (g & 1) * 8 + lr) * STRIDE + (g >> 1) * 8;
#pragma unroll
    for (int nb = 0; nb < 2; nb++)
        b_off[nb] = (128 + wn + nb * 16 + (g >> 1) * 8 + lr) * STRIDE + (g & 1) * 8;

    float acc[4][4][4];
#pragma unroll
    for (int i = 0; i < 4; i++)
#pragma unroll
        for (int j = 0; j < 4; j++)
#pragma unroll
            for (int k = 0; k < 4; k++) acc[i][j][k] = 0.0f;

    // logical K-tripling: region 0:[xh,wh] 1:[xh,wl] 2:[xl,wh]
    auto load_stage = [&](int s, int kt) {
        const int k0 = kt * 64;
        const int region = k0 >> 8;
        const int koff = k0 & 255;
        const __half* Asrc = (region < 2) ? Xh : Xl;
        const __half* Bsrc = (region == 1) ? Wl : Wh;
#pragma unroll
        for (int i = 0; i < 8; i++) {
            const int c = tid + i * 256;
            const int row = c >> 3, ch = (c & 7) * 8;   // halves
            const __half* gp;
            if (row < 128)
                gp = Asrc + (size_t)(mblk * 128 + row) * IDIM + koff + ch;
            else
                gp = Bsrc + (size_t)(nblk * 128 + (row - 128)) * IDIM + koff + ch;
            cp16(smb + (uint32_t)(s * G1_STAGE + row * STRIDE + ch) * 2, gp);
        }
    };

    load_stage(0, 0);
    CP_COMMIT();
    for (int kt = 0; kt < G1_NK; kt++) {
        CP_WAIT0();
        __syncthreads();        // stage kt visible to all; prev compute done
        if (kt + 1 < G1_NK) load_stage((kt + 1) & 1, kt + 1);
        CP_COMMIT();            // these loads overlap the compute below
        const uint32_t stg = smb + (uint32_t)((kt & 1) * G1_STAGE) * 2;
#pragma unroll
        for (int kk = 0; kk < 64; kk += 16) {
            uint32_t a[4][4], b[4][2];
#pragma unroll
            for (int ma = 0; ma < 4; ma++)
                ldm_x4(a[ma], stg + (uint32_t)(a_off[ma] + kk) * 2);
#pragma unroll
            for (int nb = 0; nb < 2; nb++) {
                uint32_t r[4];
                ldm_x4(r, stg + (uint32_t)(b_off[nb] + kk) * 2);
                b[2 * nb][0] = r[0]; b[2 * nb][1] = r[1];
                b[2 * nb + 1][0] = r[2]; b[2 * nb + 1][1] = r[3];
            }
#pragma unroll
            for (int ma = 0; ma < 4; ma++)
#pragma unroll
                for (int na = 0; na < 4; na++) mma_f16(acc[ma][na], a[ma], b[na]);
        }
    }

    // epilogue: +bias, IF sim + flag (smem list), write Ah
    const int gq = lane >> 2, tq = lane & 3;
#pragma unroll
    for (int na = 0; na < 4; na++) {
        const int col = nblk * 128 + wn + na * 8 + 2 * tq;
        const float bb0 = __ldg(bias + col);
        const float bb1 = __ldg(bias + col + 1);
#pragma unroll
        for (int ma = 0; ma < 4; ma++) {
            const int row0 = mblk * 128 + wm + ma * 16 + gq;
#pragma unroll
            for (int rv = 0; rv < 2; rv++) {
                const int row = row0 + rv * 8;
                bool f0 = false, f1 = false;
                const float a0 = if_sim_flag(acc[ma][na][rv * 2 + 0] + bb0, f0);
                const float a1 = if_sim_flag(acc[ma][na][rv * 2 + 1] + bb1, f1);
                const size_t pidx = (size_t)row * (HDIM / 2) + (col >> 1);
                reinterpret_cast<uint32_t*>(Ah)[pidx] = pack_h2(a0, a1);
                if (f0) {
                    const int idx = atomicAdd(&s_cnt, 1);
                    if (idx < FIX_CAP) s_list[idx] = (uint32_t)(row * 1024 + col);
                }
                if (f1) {
                    const int idx = atomicAdd(&s_cnt, 1);
                    if (idx < FIX_CAP) s_list[idx] = (uint32_t)(row * 1024 + col + 1);
                }
            }
        }
    }

    // In-CTA fixup with sequential ascending-k fp32 FMA (reference rounding).
    __syncthreads();
    int n = s_cnt;
    n = n < FIX_CAP ? n : FIX_CAP;
    for (int i = tid; i < n; i += 256) {
        const uint32_t code = s_list[i];
        const int m = code >> 10, j = code & 1023;
        const float* xr = xf + (size_t)m * IDIM;
        const float* wr = w1f + (size_t)j * IDIM;
        float accs = 0.0f;
        for (int k = 0; k < IDIM; k++) accs = fmaf(xr[k], wr[k], accs);
        const float a = if_sim(accs + __ldg(bias + j));
        Ah[(size_t)m * HDIM + j] = __float2half_rn(a);
    }
}

// --------------------------- GEMM2: fp16, 128x64, single product ------------
// out = Ah @ wh' (K=1024), + b2*(1-2^-16), fp32 row-major [., 256].
// Stage rows: [0,128) Ah, [128,192) Wh.
__global__ __launch_bounds__(256, 2)
void gemm2_f16(const __half* __restrict__ Ahg, const __half* __restrict__ Wh,
               const float* __restrict__ bias, float* __restrict__ out)
{
    extern __shared__ __half sm[];                  // 2 * G2_STAGE halves
    const uint32_t smb = (uint32_t)__cvta_generic_to_shared(sm);

    const int tid = threadIdx.x;
    const int lane = tid & 31;
    const int wid = tid >> 5;
    const int g = lane >> 3, lr = lane & 7;
    const int wm = (wid & 1) * 64, wn = (wid >> 1) * 16;
    const int mblk = blockIdx.y, nblk = blockIdx.x;

    int a_off[4];
#pragma unroll
    for (int ma = 0; ma < 4; ma++)
        a_off[ma] = (wm + ma * 16 + (g & 1) * 8 + lr) * STRIDE + (g >> 1) * 8;
    const int b_off = (128 + wn + (g >> 1) * 8 + lr) * STRIDE + (g & 1) * 8;

    float acc[4][2][4];
#pragma unroll
    for (int i = 0; i < 4; i++)
#pragma unroll
        for (int j = 0; j < 2; j++)
#pragma unroll
            for (int k = 0; k < 4; k++) acc[i][j][k] = 0.0f;

    // stage: 1536 16B-chunks, 6 per thread
    auto load_stage = [&](int s, int kt) {
        const int k0 = kt * 64;
#pragma unroll
        for (int i = 0; i < 6; i++) {
            const int c = tid + i * 256;
            const int row = c >> 3, ch = (c & 7) * 8;
            const __half* gp;
            if (row < 128)
                gp = Ahg + (size_t)(mblk * 128 + row) * HDIM + k0 + ch;
            else
                gp = Wh + (size_t)(nblk * 64 + (row - 128)) * HDIM + k0 + ch;
            cp16(smb + (uint32_t)(s * G2_STAGE + row * STRIDE + ch) * 2, gp);
        }
    };

    load_stage(0, 0);
    CP_COMMIT();
    for (int kt = 0; kt < G2_NK; kt++) {
        CP_WAIT0();
        __syncthreads();
        if (kt + 1 < G2_NK) load_stage((kt + 1) & 1, kt + 1);
        CP_COMMIT();
        const uint32_t stg = smb + (uint32_t)((kt & 1) * G2_STAGE) * 2;
#pragma unroll
        for (int kk = 0; kk < 64; kk += 16) {
            uint32_t a[4][4], b[2][2];
#pragma unroll
            for (int ma = 0; ma < 4; ma++)
                ldm_x4(a[ma], stg + (uint32_t)(a_off[ma] + kk) * 2);
            {
                uint32_t r[4];
                ldm_x4(r, stg + (uint32_t)(b_off + kk) * 2);
                b[0][0] = r[0]; b[0][1] = r[1];
                b[1][0] = r[2]; b[1][1] = r[3];
            }
#pragma unroll
            for (int ma = 0; ma < 4; ma++)
#pragma unroll
                for (int na = 0; na < 2; na++) mma_f16(acc[ma][na], a[ma], b[na]);
        }
    }

    const float BSCALE = 1.0f - 0x1p-16f;
    const int gq = lane >> 2, tq = lane & 3;
#pragma unroll
    for (int na = 0; na < 2; na++) {
        const int col = nblk * 64 + wn + na * 8 + 2 * tq;
        const float bb0 = __ldg(bias + col) * BSCALE;
        const float bb1 = __ldg(bias + col + 1) * BSCALE;
#pragma unroll
        for (int ma = 0; ma < 4; ma++) {
            const int row0 = mblk * 128 + wm + ma * 16 + gq;
            *reinterpret_cast<float2*>(out + (size_t)row0 * ODIM + col) =
                make_float2(acc[ma][na][0] + bb0, acc[ma][na][1] + bb1);
            *reinterpret_cast<float2*>(out + (size_t)(row0 + 8) * ODIM + col) =
                make_float2(acc[ma][na][2] + bb0, acc[ma][na][3] + bb1);
        }
    }
}

// --------------------------- launch -----------------------------------------
extern "C" void kernel_launch(void* const* d_in, const int* in_sizes, int n_in,
                              void* d_out, int out_size)
{
    const float* x  = (const float*)d_in[0];   // [8192, 256]
    const float* w1 = (const float*)d_in[1];   // [1024, 256]
    const float* b1 = (const float*)d_in[2];   // [1024]
    const float* w2 = (const float*)d_in[3];   // [256, 1024]
    const float* b2 = (const float*)d_in[4];   // [256]
    float* out = (float*)d_out;                // [8192, 256]

    __half *xh, *xl, *w1h, *w1l, *w2h, *Ah;
    cudaGetSymbolAddress((void**)&xh,  g_xh);
    cudaGetSymbolAddress((void**)&xl,  g_xl);
    cudaGetSymbolAddress((void**)&w1h, g_w1h);
    cudaGetSymbolAddress((void**)&w1l, g_w1l);
    cudaGetSymbolAddress((void**)&w2h, g_w2h);
    cudaGetSymbolAddress((void**)&Ah,  g_Ah);

    cudaFuncSetAttribute(gemm1_f16,
                         cudaFuncAttributeMaxDynamicSharedMemorySize, G1_SMEM);
    cudaFuncSetAttribute(gemm2_f16,
                         cudaFuncAttributeMaxDynamicSharedMemorySize, G2_SMEM);

    conv_all_kernel<<<CONV_TOTAL / 256, 256>>>(x, w1, w2, xh, xl, w1h, w1l, w2h);

    gemm1_f16<<<dim3(HDIM / 128, MDIM / 128), 256, G1_SMEM>>>(
        xh, xl, w1h, w1l, b1, Ah, x, w1);

    gemm2_f16<<<dim3(ODIM / 64, MDIM / 128), 256, G2_SMEM>>>(
        Ah, w2h, b2, out);
}